// round 7
// baseline (speedup 1.0000x reference)
#include <cuda_runtime.h>
#include <math.h>

#define NFFT      512
#define HOP       128
#define T_FRAMES  2048
#define F_BINS    257
#define OUT_LEN   262016       // (T-1)*HOP
#define CHUNK     2048         // output samples per block (= 16 hops)
#define OA_LEN    2816         // 128*18 + 512
#define NBC       32           // B*C

struct __align__(16) Smem {
    float   oa[4][OA_LEN];     // 4 overlap classes (plain stores)  45056 B
    float2  e512[NFFT];        // e^{+i 2 pi t / 512}                4096 B
    float   win[NFFT];         // window                             2048 B
};                             // total 51200 B -> 4 blocks/SM

__device__ __forceinline__ float2 cmul(float2 a, float2 b) {
    return make_float2(a.x * b.x - a.y * b.y, a.x * b.y + a.y * b.x);
}
__device__ __forceinline__ float2 cadd(float2 a, float2 b) {
    return make_float2(a.x + b.x, a.y + b.y);
}
__device__ __forceinline__ float2 csub(float2 a, float2 b) {
    return make_float2(a.x - b.x, a.y - b.y);
}

__global__ void __launch_bounds__(256, 4)
istft_kernel(const float* __restrict__ X,
             const float* __restrict__ window,
             float* __restrict__ out)
{
    extern __shared__ char smraw[];
    Smem& sm = *reinterpret_cast<Smem*>(smraw);

    const int tid  = threadIdx.x;      // 0..255
    const int warp = tid >> 5;         // 0..7
    const int lane = tid & 31;
    const int bc   = blockIdx.y;       // 0..31
    const int o0   = blockIdx.x * CHUNK;

    int t_lo = (o0 - 128) >> 7; if (t_lo < 0) t_lo = 0;
    int t_hi = (o0 + CHUNK + 255) >> 7; if (t_hi > T_FRAMES - 1) t_hi = T_FRAMES - 1;
    const int nt = t_hi - t_lo + 1;    // <= 19

    // ---- tables ----
    for (int i = tid; i < NFFT; i += 256) {
        float s, c;
        sincosf((float)(2.0 * M_PI / NFFT) * (float)i, &s, &c);
        sm.e512[i] = make_float2(c, s);
        sm.win[i]  = window[i];
    }
    // ---- zero overlap-add classes ----
    {
        float4* p = reinterpret_cast<float4*>(&sm.oa[0][0]);
        for (int i = tid; i < 4 * OA_LEN / 4; i += 256)
            p[i] = make_float4(0.f, 0.f, 0.f, 0.f);
    }
    __syncthreads();

    const int n1 = __brev(lane) >> 27;   // bit-reversed lane = output segment

    // X viewed as float2[(bc*F + k)*T + t]
    const float2* Xbc = reinterpret_cast<const float2*>(X)
                        + (size_t)bc * F_BINS * T_FRAMES;

    // ---- frames: warp w handles fr = w, w+8, w+16 -> class buffer (w&3) ----
    float* oacls = sm.oa[warp & 3];

    for (int fr = warp; fr < nt; fr += 8) {
        const int t = t_lo + fr;
        float2 z[8];

        // gather spectra for this frame straight from GMEM (L2 coalesces
        // across consecutive-t frames within the block), then preprocess.
        float2 av[8], bv[8];
        #pragma unroll
        for (int r = 0; r < 8; r++) {
            const int k = lane + 32 * r;
            av[r] = __ldg(&Xbc[(size_t)k * T_FRAMES + t]);
            bv[r] = __ldg(&Xbc[(size_t)(256 - k) * T_FRAMES + t]);
        }

        // preprocess: Z[k] for k = lane + 32r  (irfft real-packing)
        #pragma unroll
        for (int r = 0; r < 8; r++) {
            const int k = lane + 32 * r;
            float2 a = av[r], b = bv[r];
            if (k == 0) { a.y = 0.f; b.y = 0.f; }
            const float zer = 0.5f * (a.x + b.x);
            const float zei = 0.5f * (a.y - b.y);
            const float tr  = 0.5f * (a.x - b.x);
            const float ti  = 0.5f * (a.y + b.y);
            const float2 w  = sm.e512[k];
            const float zor = w.x * tr - w.y * ti;
            const float zoi = w.x * ti + w.y * tr;
            z[r] = make_float2(zer - zoi, zei + zor);
        }

        // ---- Step A: 8-point IDFT over registers (r -> n2) ----
        {
            const float S = 0.70710678118654752f;
            float2 t0 = cadd(z[0], z[4]), t1 = csub(z[0], z[4]);
            float2 t2 = cadd(z[2], z[6]), t3 = csub(z[2], z[6]);
            float2 E0 = cadd(t0, t2), E2 = csub(t0, t2);
            float2 it3 = make_float2(-t3.y, t3.x);
            float2 E1 = cadd(t1, it3), E3 = csub(t1, it3);

            float2 u0 = cadd(z[1], z[5]), u1 = csub(z[1], z[5]);
            float2 u2 = cadd(z[3], z[7]), u3 = csub(z[3], z[7]);
            float2 O0 = cadd(u0, u2), O2 = csub(u0, u2);
            float2 iu3 = make_float2(-u3.y, u3.x);
            float2 O1 = cadd(u1, iu3), O3 = csub(u1, iu3);

            float2 W1O1 = make_float2(S * (O1.x - O1.y), S * (O1.x + O1.y));
            float2 iO2  = make_float2(-O2.y, O2.x);
            float2 W3O3 = make_float2(-S * (O3.x + O3.y), S * (O3.x - O3.y));

            z[0] = cadd(E0, O0);   z[4] = csub(E0, O0);
            z[1] = cadd(E1, W1O1); z[5] = csub(E1, W1O1);
            z[2] = cadd(E2, iO2);  z[6] = csub(E2, iO2);
            z[3] = cadd(E3, W3O3); z[7] = csub(E3, W3O3);
        }

        // ---- Step B: twiddle W256^{n2 * lane} via independent table loads ----
        #pragma unroll
        for (int r = 1; r < 8; r++)
            z[r] = cmul(z[r], sm.e512[(2 * lane * r) & (NFFT - 1)]);

        // ---- Step C: 32-point IDFT across lanes (5 shfl_xor stages, DIF) ----
        #pragma unroll
        for (int s = 0; s < 5; s++) {
            const int h = 16 >> s;
            const bool hi = (lane & h) != 0;
            const int j = lane & (h - 1);
            const float2 w = sm.e512[hi ? j * (16 << s) : 0];  // e512[0] = (1,0)
            #pragma unroll
            for (int r = 0; r < 8; r++) {
                float2 a = z[r];
                float2 b;
                b.x = __shfl_xor_sync(0xffffffffu, a.x, h);
                b.y = __shfl_xor_sync(0xffffffffu, a.y, h);
                float2 d = hi ? csub(b, a) : cadd(a, b);
                z[r] = cmul(d, w);
            }
        }
        // lane p holds y[2*n2 + 16*brev5(p)] (Re) / y[...+1] (Im), n2 = reg

        // ---- window (from smem) + plain store (disjoint within class) ----
        const float4* w4 = reinterpret_cast<const float4*>(&sm.win[16 * n1]);
        float4* dst = reinterpret_cast<float4*>(&oacls[fr * HOP + 16 * n1]);
        #pragma unroll
        for (int q = 0; q < 4; q++) {
            const float4 wq = w4[q];
            float4 v;
            v.x = z[2 * q].x     * wq.x * (1.0f / 256.0f);
            v.y = z[2 * q].y     * wq.y * (1.0f / 256.0f);
            v.z = z[2 * q + 1].x * wq.z * (1.0f / 256.0f);
            v.w = z[2 * q + 1].y * wq.w * (1.0f / 256.0f);
            dst[q] = v;
        }
    }

    __syncthreads();

    // ---- envelope normalize + coalesced write ----
    float* outbc = out + (size_t)bc * OUT_LEN;
    const int oabase = t_lo * HOP;
    for (int jj = tid; jj < CHUNK; jj += 256) {
        const int j = o0 + jj;
        if (j >= OUT_LEN) break;
        const int i  = j + NFFT / 2;
        const int r  = i & (HOP - 1);
        const int bt = i >> 7;
        float env = 0.0f;
        #pragma unroll
        for (int s2 = 0; s2 < 4; s2++) {
            const int t = bt - s2;
            if (t >= 0 && t <= T_FRAMES - 1) {
                const float wv = sm.win[r + 128 * s2];
                env += wv * wv;
            }
        }
        const int ii = i - oabase;
        const float v = sm.oa[0][ii] + sm.oa[1][ii] + sm.oa[2][ii] + sm.oa[3][ii];
        outbc[j] = __fdividef(v, env);
    }
}

extern "C" void kernel_launch(void* const* d_in, const int* in_sizes, int n_in,
                              void* d_out, int out_size)
{
    const float* X   = (const float*)d_in[0];
    const float* win = (const float*)d_in[1];
    float* out       = (float*)d_out;

    cudaFuncSetAttribute(istft_kernel,
                         cudaFuncAttributeMaxDynamicSharedMemorySize,
                         (int)sizeof(Smem));

    dim3 grid(OUT_LEN / CHUNK + ((OUT_LEN % CHUNK) ? 1 : 0), NBC);  // (128, 32)
    istft_kernel<<<grid, 256, sizeof(Smem)>>>(X, win, out);
}

// round 11
// speedup vs baseline: 2.2136x; 2.2136x over previous
#include <cuda_runtime.h>
#include <cuda_fp16.h>
#include <math.h>

#define NFFT      512
#define HOP       128
#define T_FRAMES  2048
#define F_BINS    257
#define OUT_LEN   262016       // (T-1)*HOP
#define CHUNK     2048         // output samples per block (= 16 hops)
#define MAXFR     19           // frames touching one chunk
#define OA_LEN    2816         // 128*18 + 512
#define NBC       32           // B*C

struct __align__(16) Smem {
    __half  oa[4][OA_LEN];          // 4 overlap classes, fp16          22528 B
    __half2 stage[MAXFR * F_BINS];  // staged spectra, fp16             19532 B
    float2  e512[NFFT];             // e^{+i 2 pi t / 512}               4096 B
    float   win[NFFT];              // window                            2048 B
};                                  // ~48.2 KB -> 4 blocks/SM

__device__ __forceinline__ float2 cmul(float2 a, float2 b) {
    return make_float2(a.x * b.x - a.y * b.y, a.x * b.y + a.y * b.x);
}
__device__ __forceinline__ float2 cadd(float2 a, float2 b) {
    return make_float2(a.x + b.x, a.y + b.y);
}
__device__ __forceinline__ float2 csub(float2 a, float2 b) {
    return make_float2(a.x - b.x, a.y - b.y);
}

__global__ void __launch_bounds__(256, 4)
istft_kernel(const float* __restrict__ X,
             const float* __restrict__ window,
             float* __restrict__ out)
{
    extern __shared__ char smraw[];
    Smem& sm = *reinterpret_cast<Smem*>(smraw);

    const int tid  = threadIdx.x;      // 0..255
    const int warp = tid >> 5;         // 0..7
    const int lane = tid & 31;
    const int bc   = blockIdx.y;       // 0..31
    const int o0   = blockIdx.x * CHUNK;

    int t_lo = (o0 - 128) >> 7; if (t_lo < 0) t_lo = 0;
    int t_hi = (o0 + CHUNK + 255) >> 7; if (t_hi > T_FRAMES - 1) t_hi = T_FRAMES - 1;
    const int nt = t_hi - t_lo + 1;    // <= 19

    // ---- tables ----
    for (int i = tid; i < NFFT; i += 256) {
        float s, c;
        sincosf((float)(2.0 * M_PI / NFFT) * (float)i, &s, &c);
        sm.e512[i] = make_float2(c, s);
        sm.win[i]  = window[i];
    }
    // ---- zero overlap-add classes (fp16: 22528 B = 1408 float4) ----
    {
        float4* p = reinterpret_cast<float4*>(&sm.oa[0][0]);
        for (int i = tid; i < (int)(4 * OA_LEN * sizeof(__half) / 16); i += 256)
            p[i] = make_float4(0.f, 0.f, 0.f, 0.f);
    }

    // ---- stage spectra (fp16): one warp per k-row, lanes sweep frames ----
    const float2* Xbc = reinterpret_cast<const float2*>(X)
                        + (size_t)bc * F_BINS * T_FRAMES;
    for (int k = warp; k < F_BINS; k += 8) {
        if (lane < nt) {
            float2 v = Xbc[(size_t)k * T_FRAMES + t_lo + lane];
            sm.stage[lane * F_BINS + k] = __floats2half2_rn(v.x, v.y);
        }
    }
    __syncthreads();

    const int n1 = __brev(lane) >> 27;   // bit-reversed lane = output segment

    // ---- frames: warp w handles fr = w, w+8, w+16 -> class buffer (w&3) ----
    __half* oacls = sm.oa[warp & 3];

    for (int fr = warp; fr < nt; fr += 8) {
        const __half2* spec = &sm.stage[fr * F_BINS];
        float2 z[8];

        // preprocess: Z[k] for k = lane + 32r  (irfft real-packing)
        #pragma unroll
        for (int r = 0; r < 8; r++) {
            const int k = lane + 32 * r;
            float2 a = __half22float2(spec[k]);
            float2 b = __half22float2(spec[256 - k]);
            if (k == 0) { a.y = 0.f; b.y = 0.f; }
            const float zer = 0.5f * (a.x + b.x);
            const float zei = 0.5f * (a.y - b.y);
            const float tr  = 0.5f * (a.x - b.x);
            const float ti  = 0.5f * (a.y + b.y);
            const float2 w  = sm.e512[k];
            const float zor = w.x * tr - w.y * ti;
            const float zoi = w.x * ti + w.y * tr;
            z[r] = make_float2(zer - zoi, zei + zor);
        }

        // ---- Step A: 8-point IDFT over registers (r -> n2) ----
        {
            const float S = 0.70710678118654752f;
            float2 t0 = cadd(z[0], z[4]), t1 = csub(z[0], z[4]);
            float2 t2 = cadd(z[2], z[6]), t3 = csub(z[2], z[6]);
            float2 E0 = cadd(t0, t2), E2 = csub(t0, t2);
            float2 it3 = make_float2(-t3.y, t3.x);
            float2 E1 = cadd(t1, it3), E3 = csub(t1, it3);

            float2 u0 = cadd(z[1], z[5]), u1 = csub(z[1], z[5]);
            float2 u2 = cadd(z[3], z[7]), u3 = csub(z[3], z[7]);
            float2 O0 = cadd(u0, u2), O2 = csub(u0, u2);
            float2 iu3 = make_float2(-u3.y, u3.x);
            float2 O1 = cadd(u1, iu3), O3 = csub(u1, iu3);

            float2 W1O1 = make_float2(S * (O1.x - O1.y), S * (O1.x + O1.y));
            float2 iO2  = make_float2(-O2.y, O2.x);
            float2 W3O3 = make_float2(-S * (O3.x + O3.y), S * (O3.x - O3.y));

            z[0] = cadd(E0, O0);   z[4] = csub(E0, O0);
            z[1] = cadd(E1, W1O1); z[5] = csub(E1, W1O1);
            z[2] = cadd(E2, iO2);  z[6] = csub(E2, iO2);
            z[3] = cadd(E3, W3O3); z[7] = csub(E3, W3O3);
        }

        // ---- Step B: twiddle W256^{n2 * lane} via independent table loads ----
        #pragma unroll
        for (int r = 1; r < 8; r++)
            z[r] = cmul(z[r], sm.e512[(2 * lane * r) & (NFFT - 1)]);

        // ---- Step C: 32-point IDFT across lanes (5 shfl_xor stages, DIF) ----
        #pragma unroll
        for (int s = 0; s < 5; s++) {
            const int h = 16 >> s;
            const bool hi = (lane & h) != 0;
            const int j = lane & (h - 1);
            const float2 w = sm.e512[hi ? j * (16 << s) : 0];  // e512[0] = (1,0)
            #pragma unroll
            for (int r = 0; r < 8; r++) {
                float2 a = z[r];
                float2 b;
                b.x = __shfl_xor_sync(0xffffffffu, a.x, h);
                b.y = __shfl_xor_sync(0xffffffffu, a.y, h);
                float2 d = hi ? csub(b, a) : cadd(a, b);
                z[r] = cmul(d, w);
            }
        }
        // lane p holds y[2*n2 + 16*brev5(p)] (Re) / y[...+1] (Im), n2 = reg

        // ---- window + fp16 pack + plain store (disjoint within class) ----
        const float4* w4 = reinterpret_cast<const float4*>(&sm.win[16 * n1]);
        uint4* dst = reinterpret_cast<uint4*>(&oacls[fr * HOP + 16 * n1]);  // 16B-aligned
        #pragma unroll
        for (int half16 = 0; half16 < 2; half16++) {   // two uint4 = 2 x 8 halves
            uint4 pk;
            unsigned int* pw = reinterpret_cast<unsigned int*>(&pk);
            #pragma unroll
            for (int q = 0; q < 2; q++) {
                const int qq = 2 * half16 + q;
                const float4 wq = w4[qq];
                __half2 h0 = __floats2half2_rn(z[2 * qq].x     * wq.x * (1.0f / 256.0f),
                                               z[2 * qq].y     * wq.y * (1.0f / 256.0f));
                __half2 h1 = __floats2half2_rn(z[2 * qq + 1].x * wq.z * (1.0f / 256.0f),
                                               z[2 * qq + 1].y * wq.w * (1.0f / 256.0f));
                pw[2 * q]     = *reinterpret_cast<unsigned int*>(&h0);
                pw[2 * q + 1] = *reinterpret_cast<unsigned int*>(&h1);
            }
            dst[half16] = pk;
        }
    }

    __syncthreads();

    // ---- envelope normalize + coalesced write ----
    float* outbc = out + (size_t)bc * OUT_LEN;
    const int oabase = t_lo * HOP;
    for (int jj = tid; jj < CHUNK; jj += 256) {
        const int j = o0 + jj;
        if (j >= OUT_LEN) break;
        const int i  = j + NFFT / 2;
        const int r  = i & (HOP - 1);
        const int bt = i >> 7;
        float env = 0.0f;
        #pragma unroll
        for (int s2 = 0; s2 < 4; s2++) {
            const int t = bt - s2;
            if (t >= 0 && t <= T_FRAMES - 1) {
                const float wv = sm.win[r + 128 * s2];
                env += wv * wv;
            }
        }
        const int ii = i - oabase;
        const float v = __half2float(sm.oa[0][ii]) + __half2float(sm.oa[1][ii])
                      + __half2float(sm.oa[2][ii]) + __half2float(sm.oa[3][ii]);
        outbc[j] = __fdividef(v, env);
    }
}

extern "C" void kernel_launch(void* const* d_in, const int* in_sizes, int n_in,
                              void* d_out, int out_size)
{
    const float* X   = (const float*)d_in[0];
    const float* win = (const float*)d_in[1];
    float* out       = (float*)d_out;

    cudaFuncSetAttribute(istft_kernel,
                         cudaFuncAttributeMaxDynamicSharedMemorySize,
                         (int)sizeof(Smem));

    dim3 grid(OUT_LEN / CHUNK + ((OUT_LEN % CHUNK) ? 1 : 0), NBC);  // (128, 32)
    istft_kernel<<<grid, 256, sizeof(Smem)>>>(X, win, out);
}

// round 14
// speedup vs baseline: 2.9624x; 1.3383x over previous
#include <cuda_runtime.h>
#include <cuda_fp16.h>
#include <math.h>

#define NFFT      512
#define HOP       128
#define T_FRAMES  2048
#define F_BINS    257
#define OUT_LEN   262016       // (T-1)*HOP
#define CHUNK     2048         // output samples per block (= 16 hops)
#define MAXFR     19           // frames touching one chunk
#define OA_LEN    2816         // 128*18 + 512 (halves per class)
#define NBC       32           // B*C

struct __align__(16) Smem {
    __half  oa[4][OA_LEN];              // 4 overlap classes, fp16       22528 B
    __half2 stage[MAXFR * F_BINS + 1];  // staged spectra (+pad align)   19536 B
    float2  twtab[5 * 32];              // StepC twiddles per (s,lane)    1280 B
    float   winst[32 * 20];             // win/256, lane-permuted, pad20  2560 B
    float   win[NFFT];                  // raw window (envelope)          2048 B
};                                      // 47952 B -> 4 blocks/SM

__device__ __forceinline__ float2 cmul(float2 a, float2 b) {
    return make_float2(a.x * b.x - a.y * b.y, a.x * b.y + a.y * b.x);
}
__device__ __forceinline__ float2 cadd(float2 a, float2 b) {
    return make_float2(a.x + b.x, a.y + b.y);
}
__device__ __forceinline__ float2 csub(float2 a, float2 b) {
    return make_float2(a.x - b.x, a.y - b.y);
}

__global__ void __launch_bounds__(256, 4)
istft_kernel(const float* __restrict__ X,
             const float* __restrict__ window,
             float* __restrict__ out)
{
    extern __shared__ char smraw[];
    Smem& sm = *reinterpret_cast<Smem*>(smraw);

    const int tid  = threadIdx.x;      // 0..255
    const int warp = tid >> 5;         // 0..7
    const int lane = tid & 31;
    const int bc   = blockIdx.y;       // 0..31
    const int o0   = blockIdx.x * CHUNK;

    int t_lo = (o0 - 128) >> 7; if (t_lo < 0) t_lo = 0;
    int t_hi = (o0 + CHUNK + 255) >> 7; if (t_hi > T_FRAMES - 1) t_hi = T_FRAMES - 1;
    const int nt = t_hi - t_lo + 1;    // <= 19

    // ---- tables ----
    for (int i = tid; i < NFFT; i += 256)
        sm.win[i] = window[i];
    for (int i = tid; i < 512; i += 256) {          // winst: lane-permuted, scaled
        const int l = i >> 4, j = i & 15;
        const int n1l = __brev(l) >> 27;
        sm.winst[l * 20 + j] = window[16 * n1l + j] * (1.0f / 256.0f);
    }
    for (int i = tid; i < 160; i += 256) {          // StepC twiddles (s, lane)
        const int s = i >> 5, l = i & 31;
        const int h = 16 >> s;
        float2 v = make_float2(1.f, 0.f);
        if (l & h) {
            const int idx = (l & (h - 1)) * (16 << s);
            float ss, cc;
            sincosf((float)(2.0 * M_PI / NFFT) * (float)idx, &ss, &cc);
            v = make_float2(cc, ss);
        }
        sm.twtab[i] = v;
    }
    // ---- zero overlap-add classes ----
    {
        float4* p = reinterpret_cast<float4*>(&sm.oa[0][0]);
        for (int i = tid; i < (int)(4 * OA_LEN * sizeof(__half) / 16); i += 256)
            p[i] = make_float4(0.f, 0.f, 0.f, 0.f);
    }

    // ---- stage spectra (fp16): one warp per k-row, lanes sweep frames ----
    const float2* Xbc = reinterpret_cast<const float2*>(X)
                        + (size_t)bc * F_BINS * T_FRAMES;
    for (int k = warp; k < F_BINS; k += 8) {
        if (lane < nt) {
            float2 v = Xbc[(size_t)k * T_FRAMES + t_lo + lane];
            sm.stage[lane * F_BINS + k] = __floats2half2_rn(v.x, v.y);
        }
    }
    __syncthreads();

    const int n1 = __brev(lane) >> 27;   // bit-reversed lane = output segment

    // per-lane twiddle seeds (registers, no smem)
    float sl, cl;
    sincosf((float)(2.0 * M_PI / NFFT) * (float)lane, &sl, &cl);
    const float2 wlane = make_float2(cl, sl);        // e^{+2pi i lane/512}
    const float2 w256  = cmul(wlane, wlane);         // e^{+2pi i lane/256}

    const float2 C16[8] = {                          // e^{+i pi r/8}, immediates
        {  1.f, 0.f },
        {  0.92387953251128674f, 0.38268343236508977f },
        {  0.70710678118654752f, 0.70710678118654752f },
        {  0.38268343236508977f, 0.92387953251128674f },
        {  0.f, 1.f },
        { -0.38268343236508977f, 0.92387953251128674f },
        { -0.70710678118654752f, 0.70710678118654752f },
        { -0.92387953251128674f, 0.38268343236508977f } };

    // ---- frames: warp w handles fr = w, w+8, w+16 -> class buffer (w&3) ----
    __half* oacls = sm.oa[warp & 3];

    for (int fr = warp; fr < nt; fr += 8) {
        const __half2* spec = &sm.stage[fr * F_BINS];
        float2 z[8];

        // preprocess: Z[k] for k = lane + 32r  (irfft real-packing)
        #pragma unroll
        for (int r = 0; r < 8; r++) {
            const int k = lane + 32 * r;
            float2 a = __half22float2(spec[k]);
            float2 b = __half22float2(spec[256 - k]);
            if (k == 0) { a.y = 0.f; b.y = 0.f; }
            const float zer = 0.5f * (a.x + b.x);
            const float zei = 0.5f * (a.y - b.y);
            const float tr  = 0.5f * (a.x - b.x);
            const float ti  = 0.5f * (a.y + b.y);
            const float2 w  = cmul(wlane, C16[r]);   // e^{+2pi i k/512}
            const float zor = w.x * tr - w.y * ti;
            const float zoi = w.x * ti + w.y * tr;
            z[r] = make_float2(zer - zoi, zei + zor);
        }

        // ---- Step A: 8-point IDFT over registers (r -> n2) ----
        {
            const float S = 0.70710678118654752f;
            float2 t0 = cadd(z[0], z[4]), t1 = csub(z[0], z[4]);
            float2 t2 = cadd(z[2], z[6]), t3 = csub(z[2], z[6]);
            float2 E0 = cadd(t0, t2), E2 = csub(t0, t2);
            float2 it3 = make_float2(-t3.y, t3.x);
            float2 E1 = cadd(t1, it3), E3 = csub(t1, it3);

            float2 u0 = cadd(z[1], z[5]), u1 = csub(z[1], z[5]);
            float2 u2 = cadd(z[3], z[7]), u3 = csub(z[3], z[7]);
            float2 O0 = cadd(u0, u2), O2 = csub(u0, u2);
            float2 iu3 = make_float2(-u3.y, u3.x);
            float2 O1 = cadd(u1, iu3), O3 = csub(u1, iu3);

            float2 W1O1 = make_float2(S * (O1.x - O1.y), S * (O1.x + O1.y));
            float2 iO2  = make_float2(-O2.y, O2.x);
            float2 W3O3 = make_float2(-S * (O3.x + O3.y), S * (O3.x - O3.y));

            z[0] = cadd(E0, O0);   z[4] = csub(E0, O0);
            z[1] = cadd(E1, W1O1); z[5] = csub(E1, W1O1);
            z[2] = cadd(E2, iO2);  z[6] = csub(E2, iO2);
            z[3] = cadd(E3, W3O3); z[7] = csub(E3, W3O3);
        }

        // ---- Step B: twiddle W256^{n2 * lane} via register power chain ----
        {
            float2 t = w256;
            #pragma unroll
            for (int r = 1; r < 8; r++) {
                z[r] = cmul(z[r], t);
                if (r < 7) t = cmul(t, w256);
            }
        }

        // ---- Step C: 32-point IDFT across lanes (5 shfl_xor stages, DIF) ----
        #pragma unroll
        for (int s = 0; s < 5; s++) {
            const int h = 16 >> s;
            const bool hi = (lane & h) != 0;
            const float2 w = sm.twtab[s * 32 + lane];    // conflict-free
            #pragma unroll
            for (int r = 0; r < 8; r++) {
                float2 a = z[r];
                float2 b;
                b.x = __shfl_xor_sync(0xffffffffu, a.x, h);
                b.y = __shfl_xor_sync(0xffffffffu, a.y, h);
                float2 d = hi ? csub(b, a) : cadd(a, b);
                z[r] = cmul(d, w);
            }
        }
        // lane p holds y[2*n2 + 16*brev5(p)] (Re) / y[...+1] (Im), n2 = reg

        // ---- window (lane-permuted, conflict-free) + fp16 pack + swizzled store ----
        const float4* w4 = reinterpret_cast<const float4*>(&sm.winst[lane * 20]);
        const int Abase = fr * 256 + 32 * n1;             // byte offset in class
        #pragma unroll
        for (int half16 = 0; half16 < 2; half16++) {      // two uint4 = 2 x 8 halves
            uint4 pk;
            unsigned int* pw = reinterpret_cast<unsigned int*>(&pk);
            #pragma unroll
            for (int q = 0; q < 2; q++) {
                const int qq = 2 * half16 + q;
                const float4 wq = w4[qq];
                __half2 h0 = __floats2half2_rn(z[2 * qq].x     * wq.x,
                                               z[2 * qq].y     * wq.y);
                __half2 h1 = __floats2half2_rn(z[2 * qq + 1].x * wq.z,
                                               z[2 * qq + 1].y * wq.w);
                pw[2 * q]     = *reinterpret_cast<unsigned int*>(&h0);
                pw[2 * q + 1] = *reinterpret_cast<unsigned int*>(&h1);
            }
            int Ac = Abase + 16 * half16;                 // per-chunk swizzle
            Ac ^= 16 * ((Ac >> 7) & 7);
            *reinterpret_cast<uint4*>(reinterpret_cast<char*>(oacls) + Ac) = pk;
        }
    }

    __syncthreads();

    // ---- envelope normalize + coalesced write (reads apply the same swizzle) ----
    float* outbc = out + (size_t)bc * OUT_LEN;
    const int oabase = t_lo * HOP;
    const char* oabytes = reinterpret_cast<const char*>(&sm.oa[0][0]);
    for (int jj = tid; jj < CHUNK; jj += 256) {
        const int j = o0 + jj;
        if (j >= OUT_LEN) break;
        const int i  = j + NFFT / 2;
        const int r  = i & (HOP - 1);
        const int bt = i >> 7;
        float env = 0.0f;
        #pragma unroll
        for (int s2 = 0; s2 < 4; s2++) {
            const int t = bt - s2;
            if (t >= 0 && t <= T_FRAMES - 1) {
                const float wv = sm.win[r + 128 * s2];
                env += wv * wv;
            }
        }
        int b = (i - oabase) * 2;                     // byte offset within class
        b ^= 16 * ((b >> 7) & 7);                     // same swizzle as store
        float v = 0.f;
        #pragma unroll
        for (int c = 0; c < 4; c++)
            v += __half2float(*reinterpret_cast<const __half*>(
                     oabytes + c * (OA_LEN * sizeof(__half)) + b));
        outbc[j] = __fdividef(v, env);
    }
}

extern "C" void kernel_launch(void* const* d_in, const int* in_sizes, int n_in,
                              void* d_out, int out_size)
{
    const float* X   = (const float*)d_in[0];
    const float* win = (const float*)d_in[1];
    float* out       = (float*)d_out;

    cudaFuncSetAttribute(istft_kernel,
                         cudaFuncAttributeMaxDynamicSharedMemorySize,
                         (int)sizeof(Smem));

    dim3 grid(OUT_LEN / CHUNK + ((OUT_LEN % CHUNK) ? 1 : 0), NBC);  // (128, 32)
    istft_kernel<<<grid, 256, sizeof(Smem)>>>(X, win, out);
}